// round 16
// baseline (speedup 1.0000x reference)
#include <cuda_runtime.h>
#include <cuda_fp16.h>
#include <cstdint>

#define NROWS 16384   // C*N
#define NCOLS 4096    // N
#define OUTF  128

// ---------------- device globals (scratch; no allocations allowed) ----------------
__device__ double g_sum;
__device__ int    g_colmax[NCOLS];            // float bits as int (attention >= 0)
__device__ float  g_colsum[NCOLS];
__device__ int    g_mask_mode;                // 0=int32, 1=uint8(bool), 2=float32
__device__ __half g_e[(size_t)NROWS * NCOLS]; // post-softmax+dropout attention, fp16 (128 MB)
__device__ __half g_hs[OUTF * NCOLS];         // (cscale_j * h[j][f]) stored f-major: [f][j]

// ---------------- helpers ----------------
__device__ __forceinline__ float to_tf32(float x) {
    unsigned u;
    asm("cvt.rna.tf32.f32 %0, %1;" : "=r"(u) : "f"(x));
    return __uint_as_float(u);
}

__device__ __forceinline__ void mma_f16(float* c, const unsigned* a, unsigned b0, unsigned b1) {
    asm volatile(
        "mma.sync.aligned.m16n8k16.row.col.f32.f16.f16.f32 "
        "{%0,%1,%2,%3}, {%4,%5,%6,%7}, {%8,%9}, {%0,%1,%2,%3};\n"
        : "+f"(c[0]), "+f"(c[1]), "+f"(c[2]), "+f"(c[3])
        : "r"(a[0]), "r"(a[1]), "r"(a[2]), "r"(a[3]), "r"(b0), "r"(b1));
}

__device__ __forceinline__ void mma_tf32(float* c, const unsigned* a, unsigned b0, unsigned b1) {
    asm volatile(
        "mma.sync.aligned.m16n8k8.row.col.f32.tf32.tf32.f32 "
        "{%0,%1,%2,%3}, {%4,%5,%6,%7}, {%8,%9}, {%0,%1,%2,%3};\n"
        : "+f"(c[0]), "+f"(c[1]), "+f"(c[2]), "+f"(c[3])
        : "r"(a[0]), "r"(a[1]), "r"(a[2]), "r"(a[3]), "r"(b0), "r"(b1));
}

__device__ __forceinline__ unsigned smem_u32(const void* p) {
    unsigned a;
    asm("{ .reg .u64 t; cvta.to.shared.u64 t, %1; cvt.u32.u64 %0, t; }" : "=r"(a) : "l"(p));
    return a;
}

#define CP16(dst, src) \
    asm volatile("cp.async.cg.shared.global [%0], [%1], 16;" :: "r"(dst), \
                 "l"(__cvta_generic_to_global(src)))
#define CP_COMMIT() asm volatile("cp.async.commit_group;" ::: "memory")
#define CP_WAIT1()  asm volatile("cp.async.wait_group 1;" ::: "memory")

// ---------------- kernel 0: init + mask-dtype detection (merged) ----------------
__global__ void k_initdet(const unsigned char* __restrict__ m) {
    if (blockIdx.x == 16) {
        __shared__ unsigned s1, s23;
        if (threadIdx.x == 0) { s1 = 0; s23 = 0; }
        __syncthreads();
        const uint4* p = (const uint4*)m;
        unsigned o1 = 0, o23 = 0;
#pragma unroll
        for (int i = threadIdx.x; i < 1024; i += 256) {   // 16 KB fingerprint
            uint4 v = p[i];
            o1  |= (v.x & 0xff00u) | (v.y & 0xff00u) | (v.z & 0xff00u) | (v.w & 0xff00u);
            o23 |= (v.x & 0xffff0000u) | (v.y & 0xffff0000u) |
                   (v.z & 0xffff0000u) | (v.w & 0xffff0000u);
        }
        if (o1)  atomicOr(&s1, 1u);
        if (o23) atomicOr(&s23, 1u);
        __syncthreads();
        if (threadIdx.x == 0) g_mask_mode = s1 ? 1 : (s23 ? 2 : 0);
    } else {
        int id = blockIdx.x * blockDim.x + threadIdx.x;
        if (id < NCOLS) {
            g_colmax[id] = (int)0xFF800000;
            g_colsum[id] = 0.f;
        }
        if (id == 0) g_sum = 0.0;
    }
}

// ---------------- kernel 1: global sum (double-accurate) + per-column max ----------------
__global__ __launch_bounds__(1024) void k_stats1(const float* __restrict__ att) {
    const int t = threadIdx.x;
    const int row0 = blockIdx.x * 64;
    const float4* p = (const float4*)att;
    float m0 = -1e30f, m1 = -1e30f, m2 = -1e30f, m3 = -1e30f;
    float s = 0.f;
    int base = row0 * (NCOLS / 4) + t;
#pragma unroll 4
    for (int r = 0; r < 64; r++) {
        float4 v = p[base + r * (NCOLS / 4)];
        s += (v.x + v.y) + (v.z + v.w);
        m0 = fmaxf(m0, v.x); m1 = fmaxf(m1, v.y);
        m2 = fmaxf(m2, v.z); m3 = fmaxf(m3, v.w);
    }
    atomicMax(&g_colmax[4 * t + 0], __float_as_int(m0));
    atomicMax(&g_colmax[4 * t + 1], __float_as_int(m1));
    atomicMax(&g_colmax[4 * t + 2], __float_as_int(m2));
    atomicMax(&g_colmax[4 * t + 3], __float_as_int(m3));

    for (int o = 16; o; o >>= 1) s += __shfl_down_sync(0xffffffffu, s, o);
    __shared__ float ws[32];
    int lane = t & 31, w = t >> 5;
    if (lane == 0) ws[w] = s;
    __syncthreads();
    if (t < 32) {
        double d = (double)ws[t];
        for (int o = 16; o; o >>= 1) d += __shfl_down_sync(0xffffffffu, d, o);
        if (t == 0) atomicAdd(&g_sum, d);
    }
}

// ---------------- kernel 2: colsum of exp + materialize E fp16 (8 cols/thread) ----------------
__global__ __launch_bounds__(512) void k_stats2e(const float* __restrict__ att,
                                                 const unsigned char* __restrict__ maskb) {
    const int t = threadIdx.x;            // col group: 8*t .. 8*t+7
    const int row0 = blockIdx.x * 32;
    const float mean = (float)(g_sum / (double)((long long)NROWS * NCOLS));
    const int mode = g_mask_mode;
    const int j0 = 8 * t;

    float cm[8], cs[8];
    {
        int4 a = *(const int4*)&g_colmax[j0];
        int4 b = *(const int4*)&g_colmax[j0 + 4];
        cm[0] = __int_as_float(a.x); cm[1] = __int_as_float(a.y);
        cm[2] = __int_as_float(a.z); cm[3] = __int_as_float(a.w);
        cm[4] = __int_as_float(b.x); cm[5] = __int_as_float(b.y);
        cm[6] = __int_as_float(b.z); cm[7] = __int_as_float(b.w);
    }
#pragma unroll
    for (int i = 0; i < 8; i++) cs[i] = 0.f;

#pragma unroll 4
    for (int r = 0; r < 32; r++) {
        const int gi = (row0 + r) * NCOLS + j0;
        float4 v0 = *(const float4*)(att + gi);
        float4 v1 = *(const float4*)(att + gi + 4);
        float v[8] = {v0.x, v0.y, v0.z, v0.w, v1.x, v1.y, v1.z, v1.w};
        bool k[8];
        if (mode == 0) {
            int4 m0 = *(const int4*)((const int*)maskb + gi);
            int4 m1 = *(const int4*)((const int*)maskb + gi + 4);
            k[0] = m0.x != 0; k[1] = m0.y != 0; k[2] = m0.z != 0; k[3] = m0.w != 0;
            k[4] = m1.x != 0; k[5] = m1.y != 0; k[6] = m1.z != 0; k[7] = m1.w != 0;
        } else if (mode == 1) {
            uint2 mm = *(const uint2*)(maskb + gi);
#pragma unroll
            for (int i = 0; i < 4; i++) k[i] = ((mm.x >> (8 * i)) & 0xffu) != 0;
#pragma unroll
            for (int i = 0; i < 4; i++) k[4 + i] = ((mm.y >> (8 * i)) & 0xffu) != 0;
        } else {
            float4 m0 = *(const float4*)((const float*)maskb + gi);
            float4 m1 = *(const float4*)((const float*)maskb + gi + 4);
            k[0] = m0.x != 0.f; k[1] = m0.y != 0.f; k[2] = m0.z != 0.f; k[3] = m0.w != 0.f;
            k[4] = m1.x != 0.f; k[5] = m1.y != 0.f; k[6] = m1.z != 0.f; k[7] = m1.w != 0.f;
        }
        float e[8];
#pragma unroll
        for (int i = 0; i < 8; i++) {
            e[i] = (v[i] > mean) ? __expf(v[i] - cm[i]) : 0.f;
            cs[i] += e[i];
        }
        union { __half2 h[4]; uint4 u; } pk;
#pragma unroll
        for (int i = 0; i < 4; i++)
            pk.h[i] = __floats2half2_rn(k[2 * i] ? e[2 * i] : 0.f,
                                        k[2 * i + 1] ? e[2 * i + 1] : 0.f);
        __stcs((uint4*)(g_e + gi), pk.u);   // streaming store: don't pollute L2
    }
#pragma unroll
    for (int i = 0; i < 8; i++) atomicAdd(&g_colsum[j0 + i], cs[i]);
}

// ---------------- kernel 3: tf32 MMA  h = x @ W^T, scaled, stored f-major fp16 ----------------
// CTA: 16 nodes x 128 features, 256 threads, K-chunk 32 (16 iters over K=512); 256 CTAs
__global__ __launch_bounds__(256) void k_h(const float* __restrict__ x,
                                           const float* __restrict__ W) {
    __shared__ float As[16 * 36];    // x tile  [node][k]  (pad 36)
    __shared__ float Bs[128 * 36];   // W tile  [f][k]
    const int t = threadIdx.x;
    const int warp = t >> 5, lane = t & 31;
    const int lr = lane >> 2, lq = lane & 3;
    const int n0w = warp * 16;              // 8 warps along N(features)
    const int bm = blockIdx.x;              // 256 blocks of 16 nodes
    const int rl = t >> 3, seg = t & 7;     // A loader (threads 0-127): row rl, cols seg*4
    const int rb = t >> 1, cb = (t & 1) * 16; // B loader: row rb, cols cb..cb+15

    float acc[2][4];
#pragma unroll
    for (int b = 0; b < 2; b++)
#pragma unroll
        for (int c = 0; c < 4; c++) acc[b][c] = 0.f;

    float4 aP; float4 bP[4];
    auto LOAD = [&](int it) {
        const int k0 = it * 32;
        if (t < 128)
            aP = *(const float4*)(x + (bm * 16 + rl) * 512 + k0 + seg * 4);
        const float* wp = W + rb * 512 + k0 + cb;
        bP[0] = *(const float4*)wp;       bP[1] = *(const float4*)(wp + 4);
        bP[2] = *(const float4*)(wp + 8); bP[3] = *(const float4*)(wp + 12);
    };

    LOAD(0);
    for (int it = 0; it < 16; ++it) {
        __syncthreads();
        if (t < 128) {
            float* ad = As + rl * 36 + seg * 4;
            ad[0] = to_tf32(aP.x); ad[1] = to_tf32(aP.y);
            ad[2] = to_tf32(aP.z); ad[3] = to_tf32(aP.w);
        }
        {
            float bv[16] = {bP[0].x, bP[0].y, bP[0].z, bP[0].w,
                            bP[1].x, bP[1].y, bP[1].z, bP[1].w,
                            bP[2].x, bP[2].y, bP[2].z, bP[2].w,
                            bP[3].x, bP[3].y, bP[3].z, bP[3].w};
            float* bd = Bs + rb * 36 + cb;
#pragma unroll
            for (int i = 0; i < 16; i++) bd[i] = to_tf32(bv[i]);
        }
        __syncthreads();
        if (it + 1 < 16) LOAD(it + 1);

#pragma unroll
        for (int s = 0; s < 4; s++) {
            const int sk = s * 8;
            unsigned a[4];
            a[0] = __float_as_uint(As[lr * 36 + sk + lq]);
            a[1] = __float_as_uint(As[(lr + 8) * 36 + sk + lq]);
            a[2] = __float_as_uint(As[lr * 36 + sk + lq + 4]);
            a[3] = __float_as_uint(As[(lr + 8) * 36 + sk + lq + 4]);
#pragma unroll
            for (int ni = 0; ni < 2; ni++) {
                int nrow = n0w + ni * 8 + lr;
                unsigned b0 = __float_as_uint(Bs[nrow * 36 + sk + lq]);
                unsigned b1 = __float_as_uint(Bs[nrow * 36 + sk + lq + 4]);
                mma_tf32(acc[ni], a, b0, b1);
            }
        }
    }

    // epilogue: scale by 2.5/colsum[node], store fp16 f-major g_hs[f][n]
    {
        int n1 = bm * 16 + lr;
        int n2 = n1 + 8;
        float v1 = g_colsum[n1], v2 = g_colsum[n2];
        float cs1 = (v1 > 0.f) ? (2.5f / v1) : 0.f;
        float cs2 = (v2 > 0.f) ? (2.5f / v2) : 0.f;
#pragma unroll
        for (int ni = 0; ni < 2; ni++) {
            int f = n0w + ni * 8 + 2 * lq;
            g_hs[f * NCOLS + n1]       = __float2half(cs1 * acc[ni][0]);
            g_hs[(f + 1) * NCOLS + n1] = __float2half(cs1 * acc[ni][1]);
            g_hs[f * NCOLS + n2]       = __float2half(cs2 * acc[ni][2]);
            g_hs[(f + 1) * NCOLS + n2] = __float2half(cs2 * acc[ni][3]);
        }
    }
}

// ---------------- kernel 4: fp16 GEMM  out = E @ Hs^T, K-chunk 64, 3-stage cp.async ----------------
// CTA: M tile 64, N = 128; 256 CTAs, 256 threads, dynamic smem 83 KB, 2 CTAs/SM
#define KC      64
#define ASTRIDE 72                      // halves; 144B row stride (bank-safe)
#define A_ST    (64 * ASTRIDE)          // 4608 halves per A stage
#define B_ST    (128 * ASTRIDE)         // 9216 halves per B stage
#define GSMEM   (3 * (A_ST + B_ST) * 2) // 82944 bytes
__global__ __launch_bounds__(256, 2) void k_gemm2(float* __restrict__ out) {
    extern __shared__ __half sm[];
    __half* As = sm;
    __half* Bs = sm + 3 * A_ST;
    const int t = threadIdx.x;
    const int warp = t >> 5, lane = t & 31;
    const int lr = lane >> 2, lq = lane & 3;
    const int m0w = (warp >> 2) * 32;       // 2 warps along M
    const int n0w = (warp & 3) * 32;        // 4 warps along N
    const int bm = blockIdx.x;
    const int rl = t >> 2, seg = t & 3;     // A loader: row rl (0..63), cols seg*16 (+0,+8)
    const int rb = t >> 1, cbh = (t & 1) * 32; // B loader: row rb (0..127), cols cbh+{0,8,16,24}

    float acc[2][4][4];
#pragma unroll
    for (int a = 0; a < 2; a++)
#pragma unroll
        for (int b = 0; b < 4; b++)
#pragma unroll
            for (int c = 0; c < 4; c++) acc[a][b][c] = 0.f;

    const unsigned as0 = smem_u32(As), bs0 = smem_u32(Bs);
    const unsigned a_dst = as0 + (rl * ASTRIDE + seg * 16) * 2;
    const unsigned b_dst = bs0 + (rb * ASTRIDE + cbh) * 2;
    const __half* a_src = g_e + (size_t)(bm * 64 + rl) * NCOLS + seg * 16;
    const __half* b_src = g_hs + rb * NCOLS + cbh;

    auto ISSUE = [&](int it) {
        const int st = it % 3;
        const int col = it * KC;
        CP16(a_dst + st * A_ST * 2,      a_src + col);
        CP16(a_dst + st * A_ST * 2 + 16, a_src + col + 8);
        CP16(b_dst + st * B_ST * 2,      b_src + col);
        CP16(b_dst + st * B_ST * 2 + 16, b_src + col + 8);
        CP16(b_dst + st * B_ST * 2 + 32, b_src + col + 16);
        CP16(b_dst + st * B_ST * 2 + 48, b_src + col + 24);
    };
    ISSUE(0); CP_COMMIT();
    ISSUE(1); CP_COMMIT();

    const int arow = m0w + (lane & 7) + ((lane >> 3) & 1) * 8;
    const int acol = ((lane >> 4) & 1) * 8;

    for (int it = 0; it < NCOLS / KC; ++it) {
        CP_WAIT1();
        __syncthreads();
        if (it + 2 < NCOLS / KC) ISSUE(it + 2);
        CP_COMMIT();

        const int st = it % 3;
        const unsigned asb = as0 + st * A_ST * 2;
        const __half* bsp = Bs + st * B_ST;
#pragma unroll
        for (int kk = 0; kk < KC; kk += 16) {
            unsigned a[2][4];
#pragma unroll
            for (int mi = 0; mi < 2; mi++) {
                unsigned addr = asb + ((arow + mi * 16) * ASTRIDE + kk + acol) * 2;
                asm volatile("ldmatrix.sync.aligned.m8n8.x4.shared.b16 {%0,%1,%2,%3}, [%4];"
                             : "=r"(a[mi][0]), "=r"(a[mi][1]), "=r"(a[mi][2]), "=r"(a[mi][3])
                             : "r"(addr));
            }
#pragma unroll
            for (int ni = 0; ni < 4; ni++) {
                const int nrow = n0w + ni * 8 + lr;
                unsigned b0 = *(const unsigned*)&bsp[nrow * ASTRIDE + kk + 2 * lq];
                unsigned b1 = *(const unsigned*)&bsp[nrow * ASTRIDE + kk + 2 * lq + 8];
                mma_f16(acc[0][ni], a[0], b0, b1);
                mma_f16(acc[1][ni], a[1], b0, b1);
            }
        }
    }

    // epilogue: global row i = c*4096 + n  ->  out[n*512 + c*128 + f]
#pragma unroll
    for (int mi = 0; mi < 2; mi++) {
        int i0 = bm * 64 + m0w + mi * 16 + lr;
        int i2 = i0 + 8;
#pragma unroll
        for (int ni = 0; ni < 4; ni++) {
            int f = n0w + ni * 8 + 2 * lq;
            *(float2*)(out + (i0 & 4095) * 512 + (i0 >> 12) * 128 + f) =
                make_float2(acc[mi][ni][0], acc[mi][ni][1]);
            *(float2*)(out + (i2 & 4095) * 512 + (i2 >> 12) * 128 + f) =
                make_float2(acc[mi][ni][2], acc[mi][ni][3]);
        }
    }
}

// ---------------- launch ----------------
extern "C" void kernel_launch(void* const* d_in, const int* in_sizes, int n_in,
                              void* d_out, int out_size) {
    const float* x   = (const float*)d_in[0];
    const float* att = (const float*)d_in[1];
    const float* W   = (const float*)d_in[2];
    const unsigned char* mask = (const unsigned char*)d_in[3];
    float* out = (float*)d_out;

    static int cfg_done = 0;
    if (!cfg_done) {
        cudaFuncSetAttribute(k_gemm2, cudaFuncAttributeMaxDynamicSharedMemorySize, GSMEM);
        cfg_done = 1;
    }

    k_initdet<<<17, 256>>>(mask);
    k_stats1<<<NROWS / 64, 1024>>>(att);
    k_stats2e<<<NROWS / 32, 512>>>(att, mask);
    k_h<<<NCOLS / 16, 256>>>(x, W);
    k_gemm2<<<NROWS / 64, 256, GSMEM>>>(out);
}